// round 17
// baseline (speedup 1.0000x reference)
#include <cuda_runtime.h>
#include <stdint.h>

#define KTAPS 27
#define SELF_K 13        // (0,0,0) offset: pair_in == row, mask == 1 always
#define CCH 64
#define THREADS 256
#define MAXN 1048576     // scratch capacity (rows)
#define SPARSE_BLOCKS 592

#define F32_ONE   0x3F800000u

// Per-row packed info: {neighbor bits (bit13 unused), j0, j1, j2}.
__device__ uint4    g_info[MAXN];
// Worklist of rows with >=1 neighbor tap (order non-deterministic; each row
// is recomputed independently with fixed per-row FP order -> deterministic).
__device__ unsigned g_wl_rows[MAXN];
__device__ unsigned g_wl_count;   // reset by ksparse's last block each replay
__device__ unsigned g_done;

// ---------------- kbits: mask scan -> g_info + block-aggregated worklist ----------------
__global__ __launch_bounds__(256)
void kbits(const void* __restrict__ maskp, const void* __restrict__ pinp, int n)
{
    const unsigned* m32 = (const unsigned*)maskp;
    const unsigned w = __ldg(m32 + (size_t)SELF_K * (size_t)n);
    int mk = 0;                                   // 0 = 4-byte mask elements
    if (w != 1u && w != F32_ONE) {
        const unsigned w2 = __ldg(m32 + ((size_t)SELF_K * (size_t)n) / 2);
        if ((w2 & 0xFFFFu) == 0x3F80u) mk = 1;    // 1 = 2-byte (bf16) mask
    }
    const int* p32 = (const int*)pinp;
    const bool pw4 = (__ldg(p32 + (size_t)SELF_K * (size_t)n + 1) == 1) &&
                     (__ldg(p32 + (size_t)SELF_K * (size_t)n + 2) == 2);

    const int t   = threadIdx.x;
    const int row = blockIdx.x * 256 + t;

    unsigned bits = 0u;
    if (row < n) {
        if (mk == 0) {
            #pragma unroll
            for (int kk = 0; kk < 26; kk++) {
                const int k = kk + (kk >= SELF_K);
                if (__ldcs(m32 + (size_t)k * (size_t)n + row)) bits |= 1u << k;
            }
        } else {
            const unsigned short* m16 = (const unsigned short*)maskp;
            #pragma unroll
            for (int kk = 0; kk < 26; kk++) {
                const int k = kk + (kk >= SELF_K);
                if (__ldcs(m16 + (size_t)k * (size_t)n + row)) bits |= 1u << k;
            }
        }
    }

    // pair_in for the first <=3 set neighbor taps (ascending k); overflow
    // taps (P ~ 6e-4) are read directly by ksparse.
    unsigned j0 = 0, j1 = 0, j2 = 0;
    {
        unsigned bb = bits;
        int cnt = 0;
        while (bb && cnt < 3) {
            const int k = __ffs(bb) - 1;
            bb &= bb - 1;
            const unsigned j = pw4
                ? (unsigned)__ldg(p32 + (size_t)k * (size_t)n + row)
                : (unsigned)__ldg((const long long*)pinp + (size_t)k * (size_t)n + row);
            if (cnt == 0) j0 = j; else if (cnt == 1) j1 = j; else j2 = j;
            cnt++;
        }
    }
    if (row < n) g_info[row] = make_uint4(bits, j0, j1, j2);

    // Block-aggregated worklist append: ONE global atomic per block.
    __shared__ unsigned warp_cnt[8];
    __shared__ unsigned warp_base[8];
    __shared__ unsigned blk_base;
    const bool active = (bits != 0u);
    const int lane = t & 31;
    const int wid  = t >> 5;
    const unsigned ball = __ballot_sync(0xFFFFFFFFu, active);
    if (lane == 0) warp_cnt[wid] = (unsigned)__popc(ball);
    __syncthreads();
    if (t == 0) {
        unsigned s = 0;
        #pragma unroll
        for (int i = 0; i < 8; i++) { warp_base[i] = s; s += warp_cnt[i]; }
        blk_base = s ? atomicAdd(&g_wl_count, s) : 0u;
    }
    __syncthreads();
    if (active) {
        const unsigned slot = blk_base + warp_base[wid] +
                              (unsigned)__popc(ball & ((1u << lane) - 1u));
        g_wl_rows[slot] = (unsigned)row;
    }
}

// ---------------- kdense: out = bias + w13 * features (pure streaming) ----------------
__global__ __launch_bounds__(THREADS)
void kdense(const float* __restrict__ features,
            const float* __restrict__ weight,
            const float* __restrict__ bias,
            float* __restrict__ out,
            int n16)                      // n * 16 float4 elements
{
    const int idx = blockIdx.x * THREADS + threadIdx.x;
    if (idx >= n16) return;
    const int c4 = idx & 15;
    const float4 fv = reinterpret_cast<const float4*>(features)[idx];
    const float4 wv = __ldg(reinterpret_cast<const float4*>(weight) + SELF_K * 16 + c4);
    const float4 bv = __ldg(reinterpret_cast<const float4*>(bias) + c4);
    float4 o;
    o.x = fmaf(fv.x, wv.x, bv.x);
    o.y = fmaf(fv.y, wv.y, bv.y);
    o.z = fmaf(fv.z, wv.z, bv.z);
    o.w = fmaf(fv.w, wv.w, bv.w);
    __stcs(reinterpret_cast<float4*>(out) + idx, o);
}

// ---------------- ksparse: full recompute of worklist rows (no RMW) ----------------
__global__ __launch_bounds__(THREADS)
void ksparse(const float* __restrict__ features,
             const float* __restrict__ weight,
             const float* __restrict__ bias,
             const void* __restrict__ pinp,    // overflow taps (>3) only
             float* __restrict__ out,
             int n)
{
    const int* p32 = (const int*)pinp;
    const bool pw4 = (__ldg(p32 + (size_t)SELF_K * (size_t)n + 1) == 1) &&
                     (__ldg(p32 + (size_t)SELF_K * (size_t)n + 2) == 2);

    const unsigned total = g_wl_count;
    const int t  = threadIdx.x;
    const int r  = t >> 4;        // entry within block-slice (0..15)
    const int c4 = t & 15;

    for (unsigned e = blockIdx.x * 16u + (unsigned)r; e < total;
         e += (unsigned)gridDim.x * 16u) {
        const unsigned row  = g_wl_rows[e];
        const uint4    info = g_info[row];

        float4 acc = __ldg(reinterpret_cast<const float4*>(bias) + c4);
        unsigned blo = info.x & ((1u << SELF_K) - 1u);
        unsigned bhi = info.x >> (SELF_K + 1);
        int cnt = 0;

        // taps 0..12 (ascending, deterministic)
        while (blo) {
            const int k = __ffs(blo) - 1;
            blo &= blo - 1;
            int j;
            if      (cnt == 0) j = (int)info.y;
            else if (cnt == 1) j = (int)info.z;
            else if (cnt == 2) j = (int)info.w;
            else j = pw4 ? __ldg(p32 + (size_t)k * (size_t)n + row)
                         : (int)__ldg((const long long*)pinp + (size_t)k * (size_t)n + row);
            cnt++;
            const float4 fv = reinterpret_cast<const float4*>(features)[(size_t)j * 16 + c4];
            const float4 wv = __ldg(reinterpret_cast<const float4*>(weight) + k * 16 + c4);
            acc.x = fmaf(fv.x, wv.x, acc.x);
            acc.y = fmaf(fv.y, wv.y, acc.y);
            acc.z = fmaf(fv.z, wv.z, acc.z);
            acc.w = fmaf(fv.w, wv.w, acc.w);
        }
        // self tap (k = 13)
        {
            const float4 fv = reinterpret_cast<const float4*>(features)[(size_t)row * 16 + c4];
            const float4 wv = __ldg(reinterpret_cast<const float4*>(weight) + SELF_K * 16 + c4);
            acc.x = fmaf(fv.x, wv.x, acc.x);
            acc.y = fmaf(fv.y, wv.y, acc.y);
            acc.z = fmaf(fv.z, wv.z, acc.z);
            acc.w = fmaf(fv.w, wv.w, acc.w);
        }
        // taps 14..26
        while (bhi) {
            const int kb = __ffs(bhi) - 1;
            bhi &= bhi - 1;
            const int k = kb + SELF_K + 1;
            int j;
            if      (cnt == 0) j = (int)info.y;
            else if (cnt == 1) j = (int)info.z;
            else if (cnt == 2) j = (int)info.w;
            else j = pw4 ? __ldg(p32 + (size_t)k * (size_t)n + row)
                         : (int)__ldg((const long long*)pinp + (size_t)k * (size_t)n + row);
            cnt++;
            const float4 fv = reinterpret_cast<const float4*>(features)[(size_t)j * 16 + c4];
            const float4 wv = __ldg(reinterpret_cast<const float4*>(weight) + k * 16 + c4);
            acc.x = fmaf(fv.x, wv.x, acc.x);
            acc.y = fmaf(fv.y, wv.y, acc.y);
            acc.z = fmaf(fv.z, wv.z, acc.z);
            acc.w = fmaf(fv.w, wv.w, acc.w);
        }

        reinterpret_cast<float4*>(out)[(size_t)row * 16 + c4] = acc;
    }

    // Last-finishing block resets the worklist counter for the next replay.
    __syncthreads();
    __shared__ unsigned is_last;
    if (t == 0) {
        __threadfence();
        is_last = (atomicAdd(&g_done, 1u) == gridDim.x - 1u);
    }
    __syncthreads();
    if (is_last && t == 0) {
        g_wl_count = 0u;
        g_done = 0u;
        __threadfence();
    }
}

extern "C" void kernel_launch(void* const* d_in, const int* in_sizes, int n_in,
                              void* d_out, int out_size)
{
    // Inputs in metadata order: features, weight, bias, pair_in, pair_out,
    // pair_mask. Identify by element count; the three 27*N arrays keep their
    // metadata order (pair_in, pair_out, pair_mask).
    int fi = -1, wi = -1, bi = -1;
    int big[3], nbig = 0;
    long long maxc = -1;
    for (int i = 0; i < n_in; i++)
        if ((long long)in_sizes[i] > maxc) { maxc = in_sizes[i]; fi = i; }
    for (int i = 0; i < n_in; i++) {
        if (i == fi) continue;
        if (in_sizes[i] == 64) bi = i;
        else if (in_sizes[i] == KTAPS * CCH) wi = i;
        else if (nbig < 3) big[nbig++] = i;
    }
    const float* features = (const float*)d_in[fi];
    const float* weight   = (const float*)d_in[wi];
    const float* bias     = (const float*)d_in[bi];
    const void*  pinp     = d_in[big[0]];   // pair_in
    // big[1] = pair_out (unused: scatter target == row under mask)
    const void*  maskp    = d_in[big[2]];   // pair_mask
    float* out = (float*)d_out;

    const int n = in_sizes[fi] / CCH;
    const int n16 = n * 16;

    kbits<<<(n + 255) / 256, 256>>>(maskp, pinp, n);
    kdense<<<(n16 + THREADS - 1) / THREADS, THREADS>>>(features, weight, bias, out, n16);
    ksparse<<<SPARSE_BLOCKS, THREADS>>>(features, weight, bias, pinp, out, n);
}